// round 8
// baseline (speedup 1.0000x reference)
#include <cuda_runtime.h>
#include <math.h>
#include <stdint.h>

#define NR 3200
#define NA 320
#define TD 512
#define DD 128
#define H  128
#define B  8

#define NTF 200              // tf GEMM blocks, 16 rows each (2 rows/warp)
#define NDF 40               // df GEMM blocks, 8 rows each
#define NGEMM (NTF + NDF)
#define NB  740              // one full wave: 148 SMs x 5 blocks
#define KT  16               // k-tile for W staging
#define ZCH 8                // rows per zero-phase block claim
#define TCH 4                // rows per tanh-phase block claim

// dynamic smem: tf path: 16*TD A + KT*H W = 8192+2048 = 10240 floats = 40 KB
#define DYN_FLOATS (16 * TD + KT * H)
#define DYN_BYTES  (DYN_FLOATS * 4)

// ---------------- scratch (device globals) ----------------------------------
__device__ float g_tf[NR * H];
__device__ float g_df[NA * H];
// statically initialized; finalize resets them after use (graph replay safe)
__device__ int   g_smn[B] = {0x7F800000,0x7F800000,0x7F800000,0x7F800000,
                             0x7F800000,0x7F800000,0x7F800000,0x7F800000};
__device__ int   g_smx[B] = {0,0,0,0,0,0,0,0};
__device__ float g_dminf[B];
__device__ float g_invden[B];
__device__ int   g_gemm_done = 0;
__device__ int   g_ready     = 0;
__device__ int   g_zrow      = 0;
__device__ int   g_trow      = 0;
__device__ int   g_fin       = 0;

__device__ __forceinline__ int lowerb(const int* __restrict__ a, int n, int key) {
    int lo = 0, hi = n;
    while (lo < hi) { int m = (lo + hi) >> 1; if (a[m] < key) lo = m + 1; else hi = m; }
    return lo;
}

// ---------------- fused persistent kernel ------------------------------------
__global__ void __launch_bounds__(256, 5)
k_fused(const float* __restrict__ tfeat,
        const float* __restrict__ Wt,
        const float* __restrict__ bt,
        const float* __restrict__ dfeat,
        const float* __restrict__ Wd,
        const float* __restrict__ bd,
        const float* __restrict__ tpos,
        const float* __restrict__ dpos,
        const int* __restrict__ seg_res,
        const int* __restrict__ seg_atom,
        float* __restrict__ out) {
    extern __shared__ float buf[];
    __shared__ int  s_as8[B], s_ae8[B];
    __shared__ int  s_claim;
    __shared__ bool isLast;

    const int t = threadIdx.x;
    const int w = t >> 5, lane = t & 31;
    const int bid = blockIdx.x;

    // atom ranges per segment (seg_atom sorted)
    if (t < B) {
        s_as8[t] = lowerb(seg_atom, NA, t);
        s_ae8[t] = lowerb(seg_atom, NA, t + 1);
    }
    __syncthreads();

    // ======================= GEMM work (blocks 0..NGEMM-1) ===================
    if (bid < NTF) {
        // ---- tf GEMM: 16 rows, 2 rows/warp, Wt k-tiled (KT) in smem ----
        float* sA = buf;                                         // 16*512 floats
        float4* sW4 = reinterpret_cast<float4*>(buf + 16 * TD);  // KT*128 floats

        const int i0 = bid * 16;
        {
            const float4* src = reinterpret_cast<const float4*>(tfeat + (size_t)i0 * TD);
            float4* dst = reinterpret_cast<float4*>(sA);
            #pragma unroll
            for (int idx = t; idx < 16 * TD / 4; idx += 256) dst[idx] = src[idx];
        }

        const float* a0 = sA + (2 * w) * TD;
        const float* a1 = sA + (2 * w + 1) * TD;
        const float4* W4 = reinterpret_cast<const float4*>(Wt);
        float4 acc0 = make_float4(0.f, 0.f, 0.f, 0.f);
        float4 acc1 = make_float4(0.f, 0.f, 0.f, 0.f);

        for (int kt = 0; kt < TD; kt += KT) {
            __syncthreads();
            #pragma unroll
            for (int idx = t; idx < KT * H / 4; idx += 256)
                sW4[idx] = W4[(size_t)kt * (H / 4) + idx];
            __syncthreads();
            #pragma unroll
            for (int k = 0; k < KT; k++) {
                float4 wv = sW4[k * 32 + lane];
                float x0 = a0[kt + k], x1 = a1[kt + k];
                acc0.x = fmaf(x0, wv.x, acc0.x); acc0.y = fmaf(x0, wv.y, acc0.y);
                acc0.z = fmaf(x0, wv.z, acc0.z); acc0.w = fmaf(x0, wv.w, acc0.w);
                acc1.x = fmaf(x1, wv.x, acc1.x); acc1.y = fmaf(x1, wv.y, acc1.y);
                acc1.z = fmaf(x1, wv.z, acc1.z); acc1.w = fmaf(x1, wv.w, acc1.w);
            }
        }
        float4 bb = reinterpret_cast<const float4*>(bt)[lane];
        acc0.x += bb.x; acc0.y += bb.y; acc0.z += bb.z; acc0.w += bb.w;
        acc1.x += bb.x; acc1.y += bb.y; acc1.z += bb.z; acc1.w += bb.w;
        reinterpret_cast<float4*>(g_tf)[(size_t)(i0 + 2 * w) * 32 + lane] = acc0;
        reinterpret_cast<float4*>(g_tf)[(size_t)(i0 + 2 * w + 1) * 32 + lane] = acc1;

        // ---- per-row distance min/max -> direct global segment atomics ----
        #pragma unroll
        for (int r2 = 0; r2 < 2; r2++) {
            const int i = i0 + 2 * w + r2;
            const int b = seg_res[i];
            const int as = s_as8[b], ae = s_ae8[b];
            const float px = tpos[3 * i], py = tpos[3 * i + 1], pz = tpos[3 * i + 2];
            float mn = INFINITY, mx = 0.0f;
            for (int j = as + lane; j < ae; j += 32) {
                float dx = px - dpos[3 * j];
                float dy = py - dpos[3 * j + 1];
                float dz = pz - dpos[3 * j + 2];
                float d = sqrtf(dx * dx + dy * dy + dz * dz);
                mn = fminf(mn, d); mx = fmaxf(mx, d);
            }
            #pragma unroll
            for (int o = 16; o; o >>= 1) {
                mn = fminf(mn, __shfl_xor_sync(0xFFFFFFFFu, mn, o));
                mx = fmaxf(mx, __shfl_xor_sync(0xFFFFFFFFu, mx, o));
            }
            if (lane == 0) {
                // nonnegative floats: int compare == float compare
                atomicMin(&g_smn[b], __float_as_int(mn));
                atomicMax(&g_smx[b], __float_as_int(mx));
            }
        }
    } else if (bid < NGEMM) {
        // ---- df GEMM: 8 rows (warp-per-row), Wd k-tiled (KT) in smem ----
        float* sA = buf;                                         // 8*128 floats
        float4* sW4 = reinterpret_cast<float4*>(buf + 8 * DD);   // KT*128 floats

        const int i0 = (bid - NTF) * 8;
        {
            const float4* src = reinterpret_cast<const float4*>(dfeat + (size_t)i0 * DD);
            float4* dst = reinterpret_cast<float4*>(sA);
            for (int idx = t; idx < 8 * DD / 4; idx += 256) dst[idx] = src[idx];
        }

        const float* arow = sA + w * DD;
        const float4* W4 = reinterpret_cast<const float4*>(Wd);
        float4 acc = make_float4(0.f, 0.f, 0.f, 0.f);

        for (int kt = 0; kt < DD; kt += KT) {
            __syncthreads();
            #pragma unroll
            for (int idx = t; idx < KT * H / 4; idx += 256)
                sW4[idx] = W4[(size_t)kt * (H / 4) + idx];
            __syncthreads();
            #pragma unroll
            for (int k = 0; k < KT; k++) {
                float4 wv = sW4[k * 32 + lane];
                float x = arow[kt + k];
                acc.x = fmaf(x, wv.x, acc.x); acc.y = fmaf(x, wv.y, acc.y);
                acc.z = fmaf(x, wv.z, acc.z); acc.w = fmaf(x, wv.w, acc.w);
            }
        }
        float4 bb = reinterpret_cast<const float4*>(bd)[lane];
        acc.x += bb.x; acc.y += bb.y; acc.z += bb.z; acc.w += bb.w;
        reinterpret_cast<float4*>(g_df)[(size_t)(i0 + w) * 32 + lane] = acc;
    }

    // -------- GEMM completion: last GEMM block finalizes 8 values ------------
    if (bid < NGEMM) {
        __threadfence();
        __syncthreads();
        if (t == 0) isLast = (atomicAdd(&g_gemm_done, 1) == NGEMM - 1);
        __syncthreads();
        if (isLast && t < B) {
            float dmin = __int_as_float(__ldcg(&g_smn[t]));
            float dmax = __int_as_float(__ldcg(&g_smx[t]));
            if (!isfinite(dmin)) dmin = 0.0f;
            float den = (dmax > dmin) ? (dmax - dmin) : 1.0f;
            g_dminf[t] = dmin;
            g_invden[t] = 1.0f / den;
            // reset for next graph replay
            g_smn[t] = 0x7F800000;
            g_smx[t] = 0;
        }
        if (isLast) {
            __syncthreads();
            if (t == 0) { __threadfence(); atomicExch(&g_ready, 1); }
        }
    }

    const float4 z4 = make_float4(0.f, 0.f, 0.f, 0.f);

    // ============ Phase Z: zero stripes (block claims of ZCH rows) ===========
    for (;;) {
        __syncthreads();
        if (t == 0) s_claim = atomicAdd(&g_zrow, ZCH);
        __syncthreads();
        const int base = s_claim;
        if (base >= NR) break;
        const int end = (base + ZCH < NR) ? base + ZCH : NR;
        for (int i = base; i < end; i++) {
            const int b = seg_res[i];
            const int as = s_as8[b], ae = s_ae8[b];
            float4* out4 = reinterpret_cast<float4*>(out) + (size_t)i * (NA * H / 4);

            const int nl = as * (H / 4);
            for (int idx = t; idx < nl; idx += 256) __stcs(&out4[idx], z4);

            const int nr_ = (NA - ae) * (H / 4);
            float4* outr = out4 + ae * (H / 4);
            for (int idx = t; idx < nr_; idx += 256) __stcs(&outr[idx], z4);
        }
    }

    // ======================= wait for GEMM finalize ===========================
    if (t == 0) {
        while (((volatile int*)&g_ready)[0] == 0) __nanosleep(64);
    }
    __syncthreads();   // also fences buf reuse below
    __threadfence();

    // ============ Phase T: tanh middle (block claims of TCH rows) ============
    float* s_dn = buf;        // NA floats
    float* s_tf = buf + NA;   // H floats
    const float4* df4 = reinterpret_cast<const float4*>(g_df);

    for (;;) {
        __syncthreads();
        if (t == 0) s_claim = atomicAdd(&g_trow, TCH);
        __syncthreads();
        const int base = s_claim;
        if (base >= NR) break;
        const int end = (base + TCH < NR) ? base + TCH : NR;
        for (int i = base; i < end; i++) {
            const int b = seg_res[i];
            const int as = s_as8[b], ae = s_ae8[b];
            const int na = ae - as;
            if (na <= 0) continue;

            const float dmin = __ldcg(&g_dminf[b]);
            const float inv  = __ldcg(&g_invden[b]);

            if (t < H) s_tf[t] = __ldcg(&g_tf[(size_t)i * H + t]);

            const float px = tpos[3 * i], py = tpos[3 * i + 1], pz = tpos[3 * i + 2];
            for (int j = as + t; j < ae; j += 256) {
                float dx = px - dpos[3 * j];
                float dy = py - dpos[3 * j + 1];
                float dz = pz - dpos[3 * j + 2];
                s_dn[j - as] = (sqrtf(dx * dx + dy * dy + dz * dz) - dmin) * inv;
            }
            __syncthreads();

            float4* outm = reinterpret_cast<float4*>(out) + (size_t)i * (NA * H / 4) + as * (H / 4);
            const float4* tf4 = reinterpret_cast<const float4*>(s_tf);
            const int nm = na * (H / 4);
            for (int idx = t; idx < nm; idx += 256) {
                const int jo = idx >> 5;
                const int q  = idx & 31;
                const float dn = s_dn[jo];
                const float4 tv = tf4[q];
                const float4 dv = __ldcg(&df4[(size_t)(as + jo) * 32 + q]);
                float4 r;
                r.x = tanhf(tv.x - dv.x + dn);
                r.y = tanhf(tv.y - dv.y + dn);
                r.z = tanhf(tv.z - dv.z + dn);
                r.w = tanhf(tv.w - dv.w + dn);
                __stcs(&outm[idx], r);
            }
            __syncthreads();
        }
    }

    // ======================= finish: last block resets counters ===============
    __syncthreads();
    if (t == 0) {
        int c = atomicAdd(&g_fin, 1);
        if (c == NB - 1) {
            g_gemm_done = 0;
            g_ready = 0;
            g_zrow = 0;
            g_trow = 0;
            g_fin = 0;
        }
    }
}

// ---------------- launch -------------------------------------------------------
extern "C" void kernel_launch(void* const* d_in, const int* in_sizes, int n_in,
                              void* d_out, int out_size) {
    const float* target_feature = (const float*)d_in[0];
    const float* drug_feature   = (const float*)d_in[1];
    const float* target_pos     = (const float*)d_in[2];
    const float* drug_pos       = (const float*)d_in[3];
    const float* Wt             = (const float*)d_in[4];
    const float* bt             = (const float*)d_in[5];
    const float* Wd             = (const float*)d_in[6];
    const float* bd             = (const float*)d_in[7];
    const int*   seg_res        = (const int*)d_in[8];
    const int*   seg_atom       = (const int*)d_in[9];
    float* out = (float*)d_out;

    cudaFuncSetAttribute(k_fused, cudaFuncAttributeMaxDynamicSharedMemorySize, DYN_BYTES);

    k_fused<<<NB, 256, DYN_BYTES>>>(target_feature, Wt, bt,
                                    drug_feature, Wd, bd,
                                    target_pos, drug_pos,
                                    seg_res, seg_atom, out);
}

// round 9
// speedup vs baseline: 1.2045x; 1.2045x over previous
#include <cuda_runtime.h>
#include <math.h>
#include <stdint.h>

#define NR 3200
#define NA 320
#define TD 512
#define DD 128
#define H  128
#define B  8

#define NTF 200              // tf GEMM blocks, 16 rows each (2 rows/warp)
#define NDF 40               // df GEMM blocks, 8 rows each
#define NGEMM (NTF + NDF)
#define NB  444              // one full wave: 148 SMs x 3 blocks
#define KT  64               // k-tile for Wt staging
#define ZCH 4                // rows per claim, fused zero(+middle) phase
#define TCH 2                // rows per claim, cleanup phase

// dynamic smem: max(tf: 16*512 + 64*128, df: 128*128 + 8*128) floats = 68 KB
#define DYN_FLOATS (DD * H + 8 * DD)
#define DYN_BYTES  (DYN_FLOATS * 4)

// ---------------- scratch (device globals) ----------------------------------
__device__ float g_tf[NR * H];
__device__ float g_df[NA * H];
// statically initialized; finalize resets after use (graph replay safe)
__device__ int   g_smn[B] = {0x7F800000,0x7F800000,0x7F800000,0x7F800000,
                             0x7F800000,0x7F800000,0x7F800000,0x7F800000};
__device__ int   g_smx[B] = {0,0,0,0,0,0,0,0};
__device__ float g_dminf[B];
__device__ float g_invden[B];
__device__ unsigned char g_done[NR];   // zero-init; reset by last block each run
__device__ int   g_gemm_done = 0;
__device__ int   g_ready     = 0;
__device__ int   g_zrow      = 0;
__device__ int   g_trow      = 0;
__device__ int   g_fin       = 0;

__device__ __forceinline__ int lowerb(const int* __restrict__ a, int n, int key) {
    int lo = 0, hi = n;
    while (lo < hi) { int m = (lo + hi) >> 1; if (a[m] < key) lo = m + 1; else hi = m; }
    return lo;
}

// ---------------- fused persistent kernel ------------------------------------
__global__ void __launch_bounds__(256, 3)
k_fused(const float* __restrict__ tfeat,
        const float* __restrict__ Wt,
        const float* __restrict__ bt,
        const float* __restrict__ dfeat,
        const float* __restrict__ Wd,
        const float* __restrict__ bd,
        const float* __restrict__ tpos,
        const float* __restrict__ dpos,
        const int* __restrict__ seg_res,
        const int* __restrict__ seg_atom,
        float* __restrict__ out) {
    extern __shared__ float buf[];
    __shared__ int  s_as8[B], s_ae8[B];
    __shared__ int  s_bmn[B], s_bmx[B];
    __shared__ int  s_claim, s_flag;
    __shared__ bool isLast;

    const int t = threadIdx.x;
    const int w = t >> 5, lane = t & 31;
    const int bid = blockIdx.x;

    if (t < B) {
        s_as8[t] = lowerb(seg_atom, NA, t);
        s_ae8[t] = lowerb(seg_atom, NA, t + 1);
        s_bmn[t] = 0x7F800000;
        s_bmx[t] = 0;
    }
    __syncthreads();

    // ======================= GEMM work (blocks 0..NGEMM-1) ===================
    if (bid < NTF) {
        // ---- tf GEMM: 16 rows, 2 rows/warp, Wt k-tiled (KT=64) in smem ----
        float* sA = buf;                                         // 16*512 floats
        float4* sW4 = reinterpret_cast<float4*>(buf + 16 * TD);  // 64*128 floats

        const int i0 = bid * 16;
        {
            const float4* src = reinterpret_cast<const float4*>(tfeat + (size_t)i0 * TD);
            float4* dst = reinterpret_cast<float4*>(sA);
            #pragma unroll
            for (int idx = t; idx < 16 * TD / 4; idx += 256) dst[idx] = src[idx];
        }

        const float* a0 = sA + (2 * w) * TD;
        const float* a1 = sA + (2 * w + 1) * TD;
        const float4* W4 = reinterpret_cast<const float4*>(Wt);
        float4 acc0 = make_float4(0.f, 0.f, 0.f, 0.f);
        float4 acc1 = make_float4(0.f, 0.f, 0.f, 0.f);

        for (int kt = 0; kt < TD; kt += KT) {
            __syncthreads();
            #pragma unroll
            for (int idx = t; idx < KT * H / 4; idx += 256)
                sW4[idx] = W4[(size_t)kt * (H / 4) + idx];
            __syncthreads();
            #pragma unroll 8
            for (int k = 0; k < KT; k++) {
                float4 wv = sW4[k * 32 + lane];
                float x0 = a0[kt + k], x1 = a1[kt + k];
                acc0.x = fmaf(x0, wv.x, acc0.x); acc0.y = fmaf(x0, wv.y, acc0.y);
                acc0.z = fmaf(x0, wv.z, acc0.z); acc0.w = fmaf(x0, wv.w, acc0.w);
                acc1.x = fmaf(x1, wv.x, acc1.x); acc1.y = fmaf(x1, wv.y, acc1.y);
                acc1.z = fmaf(x1, wv.z, acc1.z); acc1.w = fmaf(x1, wv.w, acc1.w);
            }
        }
        float4 bb = reinterpret_cast<const float4*>(bt)[lane];
        acc0.x += bb.x; acc0.y += bb.y; acc0.z += bb.z; acc0.w += bb.w;
        acc1.x += bb.x; acc1.y += bb.y; acc1.z += bb.z; acc1.w += bb.w;
        reinterpret_cast<float4*>(g_tf)[(size_t)(i0 + 2 * w) * 32 + lane] = acc0;
        reinterpret_cast<float4*>(g_tf)[(size_t)(i0 + 2 * w + 1) * 32 + lane] = acc1;

        // ---- per-row distance min/max -> smem seg reduce -> global atomics --
        #pragma unroll
        for (int r2 = 0; r2 < 2; r2++) {
            const int i = i0 + 2 * w + r2;
            const int b = seg_res[i];
            const int as = s_as8[b], ae = s_ae8[b];
            const float px = tpos[3 * i], py = tpos[3 * i + 1], pz = tpos[3 * i + 2];
            float mn = INFINITY, mx = 0.0f;
            for (int j = as + lane; j < ae; j += 32) {
                float dx = px - dpos[3 * j];
                float dy = py - dpos[3 * j + 1];
                float dz = pz - dpos[3 * j + 2];
                float d = sqrtf(dx * dx + dy * dy + dz * dz);
                mn = fminf(mn, d); mx = fmaxf(mx, d);
            }
            #pragma unroll
            for (int o = 16; o; o >>= 1) {
                mn = fminf(mn, __shfl_xor_sync(0xFFFFFFFFu, mn, o));
                mx = fmaxf(mx, __shfl_xor_sync(0xFFFFFFFFu, mx, o));
            }
            if (lane == 0) {
                // nonnegative floats: int compare == float compare
                atomicMin(&s_bmn[b], __float_as_int(mn));
                atomicMax(&s_bmx[b], __float_as_int(mx));
            }
        }
        __syncthreads();
        if (t < B) {
            if (s_bmn[t] != 0x7F800000) atomicMin(&g_smn[t], s_bmn[t]);
            if (s_bmx[t] != 0)          atomicMax(&g_smx[t], s_bmx[t]);
        }
    } else if (bid < NGEMM) {
        // ---- df GEMM: 8 rows, Wd fully staged in smem ----
        float* sWd = buf;
        float* sAd = buf + DD * H;
        float4* sWd4 = reinterpret_cast<float4*>(sWd);

        const int i0 = (bid - NTF) * 8;
        {
            const float4* srcW = reinterpret_cast<const float4*>(Wd);
            #pragma unroll
            for (int idx = t; idx < DD * H / 4; idx += 256) sWd4[idx] = srcW[idx];
            const float4* srcA = reinterpret_cast<const float4*>(dfeat + (size_t)i0 * DD);
            float4* dstA = reinterpret_cast<float4*>(sAd);
            for (int idx = t; idx < 8 * DD / 4; idx += 256) dstA[idx] = srcA[idx];
        }
        __syncthreads();

        const float* arow = sAd + w * DD;
        float4 acc = make_float4(0.f, 0.f, 0.f, 0.f);
        #pragma unroll 8
        for (int k = 0; k < DD; k++) {
            float4 wv = sWd4[k * 32 + lane];
            float x = arow[k];
            acc.x = fmaf(x, wv.x, acc.x); acc.y = fmaf(x, wv.y, acc.y);
            acc.z = fmaf(x, wv.z, acc.z); acc.w = fmaf(x, wv.w, acc.w);
        }
        float4 bb = reinterpret_cast<const float4*>(bd)[lane];
        acc.x += bb.x; acc.y += bb.y; acc.z += bb.z; acc.w += bb.w;
        reinterpret_cast<float4*>(g_df)[(size_t)(i0 + w) * 32 + lane] = acc;
    }

    // -------- GEMM completion: last GEMM block finalizes 8 values ------------
    if (bid < NGEMM) {
        __threadfence();
        __syncthreads();
        if (t == 0) isLast = (atomicAdd(&g_gemm_done, 1) == NGEMM - 1);
        __syncthreads();
        if (isLast && t < B) {
            float dmin = __int_as_float(__ldcg(&g_smn[t]));
            float dmax = __int_as_float(__ldcg(&g_smx[t]));
            if (!isfinite(dmin)) dmin = 0.0f;
            float den = (dmax > dmin) ? (dmax - dmin) : 1.0f;
            g_dminf[t] = dmin;
            g_invden[t] = 1.0f / den;
            g_smn[t] = 0x7F800000;   // reset for next replay
            g_smx[t] = 0;
        }
        if (isLast) {
            __syncthreads();
            if (t == 0) { __threadfence(); atomicExch(&g_ready, 1); }
        }
    }

    const float4 z4 = make_float4(0.f, 0.f, 0.f, 0.f);
    const float4* df4 = reinterpret_cast<const float4*>(g_df);
    const float4* gtf4 = reinterpret_cast<const float4*>(g_tf);
    float* s_dn = buf;        // NA floats (GEMM use of buf is finished)
    float* s_tf = buf + NA;   // H floats
    bool ready_seen = false;

    // ============ Phase 1: zero stripes (+ middle once ready) ================
    for (;;) {
        __syncthreads();
        if (t == 0) {
            s_claim = atomicAdd(&g_zrow, ZCH);
            s_flag  = *((volatile int*)&g_ready);
        }
        __syncthreads();
        const int base = s_claim;
        const bool rdy = ready_seen || (s_flag != 0);
        if (!ready_seen && rdy) { __threadfence(); ready_seen = true; }
        if (base >= NR) break;
        const int end = (base + ZCH < NR) ? base + ZCH : NR;

        for (int i = base; i < end; i++) {
            const int b = seg_res[i];
            const int as = s_as8[b], ae = s_ae8[b];
            float4* out4 = reinterpret_cast<float4*>(out) + (size_t)i * (NA * H / 4);

            const int nl = as * (H / 4);
            for (int idx = t; idx < nl; idx += 256) __stcs(&out4[idx], z4);

            const int nr_ = (NA - ae) * (H / 4);
            float4* outr = out4 + ae * (H / 4);
            for (int idx = t; idx < nr_; idx += 256) __stcs(&outr[idx], z4);

            const int na = ae - as;
            if (rdy && na > 0) {
                const float dmin = __ldcg(&g_dminf[b]);
                const float inv  = __ldcg(&g_invden[b]);

                if (t < H) s_tf[t] = __ldcg(&g_tf[(size_t)i * H + t]);

                const float px = tpos[3 * i], py = tpos[3 * i + 1], pz = tpos[3 * i + 2];
                for (int j = as + t; j < ae; j += 256) {
                    float dx = px - dpos[3 * j];
                    float dy = py - dpos[3 * j + 1];
                    float dz = pz - dpos[3 * j + 2];
                    s_dn[j - as] = (sqrtf(dx * dx + dy * dy + dz * dz) - dmin) * inv;
                }
                __syncthreads();

                float4* outm = out4 + as * (H / 4);
                const float4* tf4 = reinterpret_cast<const float4*>(s_tf);
                const int nm = na * (H / 4);
                for (int idx = t; idx < nm; idx += 256) {
                    const int jo = idx >> 5;
                    const int q  = idx & 31;
                    const float dn = s_dn[jo];
                    const float4 tv = tf4[q];
                    const float4 dv = __ldcg(&df4[(size_t)(as + jo) * 32 + q]);
                    float4 r;
                    r.x = tanhf(tv.x - dv.x + dn);
                    r.y = tanhf(tv.y - dv.y + dn);
                    r.z = tanhf(tv.z - dv.z + dn);
                    r.w = tanhf(tv.w - dv.w + dn);
                    __stcs(&outm[idx], r);
                }
                __syncthreads();
                if (t == 0) { __threadfence(); g_done[i] = 1; }
            }
        }
    }

    // ======================= wait for GEMM finalize ===========================
    if (t == 0) {
        while (((volatile int*)&g_ready)[0] == 0) __nanosleep(64);
    }
    __syncthreads();
    __threadfence();

    // ============ Phase 2: middles for rows missed in phase 1 ================
    for (;;) {
        __syncthreads();
        if (t == 0) s_claim = atomicAdd(&g_trow, TCH);
        __syncthreads();
        const int base = s_claim;
        if (base >= NR) break;
        const int end = (base + TCH < NR) ? base + TCH : NR;
        for (int i = base; i < end; i++) {
            if (t == 0) s_flag = __ldcg(&g_done[i]);
            __syncthreads();
            if (s_flag) { __syncthreads(); continue; }

            const int b = seg_res[i];
            const int as = s_as8[b], ae = s_ae8[b];
            const int na = ae - as;
            if (na <= 0) { __syncthreads(); continue; }

            const float dmin = __ldcg(&g_dminf[b]);
            const float inv  = __ldcg(&g_invden[b]);

            if (t < H) s_tf[t] = __ldcg(&g_tf[(size_t)i * H + t]);

            const float px = tpos[3 * i], py = tpos[3 * i + 1], pz = tpos[3 * i + 2];
            for (int j = as + t; j < ae; j += 256) {
                float dx = px - dpos[3 * j];
                float dy = py - dpos[3 * j + 1];
                float dz = pz - dpos[3 * j + 2];
                s_dn[j - as] = (sqrtf(dx * dx + dy * dy + dz * dz) - dmin) * inv;
            }
            __syncthreads();

            float4* outm = reinterpret_cast<float4*>(out) + (size_t)i * (NA * H / 4) + as * (H / 4);
            const float4* tf4 = reinterpret_cast<const float4*>(s_tf);
            const int nm = na * (H / 4);
            for (int idx = t; idx < nm; idx += 256) {
                const int jo = idx >> 5;
                const int q  = idx & 31;
                const float dn = s_dn[jo];
                const float4 tv = tf4[q];
                const float4 dv = __ldcg(&df4[(size_t)(as + jo) * 32 + q]);
                float4 r;
                r.x = tanhf(tv.x - dv.x + dn);
                r.y = tanhf(tv.y - dv.y + dn);
                r.z = tanhf(tv.z - dv.z + dn);
                r.w = tanhf(tv.w - dv.w + dn);
                __stcs(&outm[idx], r);
            }
            __syncthreads();
        }
    }

    // ======================= finish: last block resets state ==================
    __threadfence();
    __syncthreads();
    if (t == 0) s_flag = (atomicAdd(&g_fin, 1) == NB - 1) ? 1 : 0;
    __syncthreads();
    if (s_flag) {
        for (int i = t; i < NR; i += 256) g_done[i] = 0;
        if (t == 0) {
            g_gemm_done = 0;
            g_ready = 0;
            g_zrow = 0;
            g_trow = 0;
            g_fin = 0;
        }
    }
}

// ---------------- launch -------------------------------------------------------
extern "C" void kernel_launch(void* const* d_in, const int* in_sizes, int n_in,
                              void* d_out, int out_size) {
    const float* target_feature = (const float*)d_in[0];
    const float* drug_feature   = (const float*)d_in[1];
    const float* target_pos     = (const float*)d_in[2];
    const float* drug_pos       = (const float*)d_in[3];
    const float* Wt             = (const float*)d_in[4];
    const float* bt             = (const float*)d_in[5];
    const float* Wd             = (const float*)d_in[6];
    const float* bd             = (const float*)d_in[7];
    const int*   seg_res        = (const int*)d_in[8];
    const int*   seg_atom       = (const int*)d_in[9];
    float* out = (float*)d_out;

    cudaFuncSetAttribute(k_fused, cudaFuncAttributeMaxDynamicSharedMemorySize, DYN_BYTES);

    k_fused<<<NB, 256, DYN_BYTES>>>(target_feature, Wt, bt,
                                    drug_feature, Wd, bd,
                                    target_pos, drug_pos,
                                    seg_res, seg_atom, out);
}